// round 12
// baseline (speedup 1.0000x reference)
#include <cuda_runtime.h>

// ---------------------------------------------------------------------------
// SSIM loss, fully fused single kernel: 5 separable 11x11 Gaussian convs +
// SSIM map + global mean. pred/target: (32,3,512,512) fp32.
// Output: scalar fp32 = 1 - mean(ssim_map).
// Instruction-count-optimized: packed fma.rn.f32x2 (FFMA2) carries signal
// pairs (mu1,mu2) and (E[p^2],E[t^2]) through both conv stages.
// ---------------------------------------------------------------------------

typedef unsigned long long ull;

namespace {
constexpr int IMG  = 512;
constexpr int TW   = 64;          // output tile width
constexpr int TH   = 16;          // output tile height (512 % 16 == 0, no tail)
constexpr int SWH  = TW + 10;     // 74  halo width
constexpr int SHH  = TH + 10;     // 26  halo height
constexpr int SWM  = 76;          // padded mid-row stride (pairs; 608B, 16B-mult)
constexpr int NT   = 256;         // threads per block
constexpr int VY   = 4;           // rows per thread in vertical pass
constexpr int HALO_PAIRS = SHH * SWH;   // 1924 (ull each: {p,t})
constexpr int MID_ELEMS  = TH * SWM;    // 1216 per buffer
// smem: halo pairs + mid01 pairs + mid23 pairs + mid4 scalar
constexpr int SMEM_BYTES = HALO_PAIRS * 8 + MID_ELEMS * 8 * 2 + MID_ELEMS * 4;
// = 15392 + 19456 + 4864 = 39712 B (~38.8KB)
constexpr float SSIM_C1 = 0.0001f;   // 0.01^2
constexpr float SSIM_C2 = 0.0009f;   // 0.03^2
constexpr int MAX_BLOCKS = 32768;
}  // namespace

// Gaussian(sigma=1.5, 11 taps), normalized; constexpr function -> literals.
__host__ __device__ __forceinline__ constexpr float gw(int k) {
    switch (k) {
        case 0: case 10: return 0.00102840f;
        case 1: case 9:  return 0.00759876f;
        case 2: case 8:  return 0.03600077f;
        case 3: case 7:  return 0.10936067f;
        case 4: case 6:  return 0.21300555f;
        default:         return 0.26601174f;
    }
}

__device__ float        g_partials[MAX_BLOCKS];
__device__ unsigned int g_ticket;   // zero-init; atomicInc wraps back to 0

// ---- packed f32x2 primitives (Blackwell FFMA2 path, PTX-only) -------------
__device__ __forceinline__ ull pack2(float lo, float hi) {
    ull r; asm("mov.b64 %0, {%1, %2};" : "=l"(r) : "f"(lo), "f"(hi)); return r;
}
__device__ __forceinline__ void unpack2(float& lo, float& hi, ull v) {
    asm("mov.b64 {%0, %1}, %2;" : "=f"(lo), "=f"(hi) : "l"(v));
}
__device__ __forceinline__ ull fma2(ull a, ull b, ull c) {
    ull d; asm("fma.rn.f32x2 %0, %1, %2, %3;" : "=l"(d) : "l"(a), "l"(b), "l"(c));
    return d;
}
__device__ __forceinline__ ull mul2(ull a, ull b) {
    ull d; asm("mul.rn.f32x2 %0, %1, %2;" : "=l"(d) : "l"(a), "l"(b)); return d;
}

// Horizontal 11-tap conv over PAIR data for 4 consecutive outputs.
// rowbase 16B aligned; x4 = output-group index (4 outputs, pair idx 4*x4).
__device__ __forceinline__ void hconv4_pair(const ull* __restrict__ rowbase,
                                            int x4, const ull* __restrict__ W2,
                                            ull out[4]) {
    const ulonglong2* r = reinterpret_cast<const ulonglong2*>(rowbase) + 2 * x4;
    ull v[16];
#pragma unroll
    for (int i = 0; i < 8; i++) { ulonglong2 q = r[i]; v[2*i] = q.x; v[2*i+1] = q.y; }
#pragma unroll
    for (int j = 0; j < 4; j++) {
        ull a = 0;
#pragma unroll
        for (int k = 0; k < 11; k++) a = fma2(v[j + k], W2[k], a);
        out[j] = a;
    }
}

// Scalar horizontal conv for the pt signal (4 outputs).
__device__ __forceinline__ void hconv4_scalar(const float* __restrict__ base,
                                              int x4, float out[4]) {
    const float4* r = reinterpret_cast<const float4*>(base) + x4;
    float4 q0 = r[0], q1 = r[1], q2 = r[2], q3 = r[3];
    float v[16] = {q0.x, q0.y, q0.z, q0.w, q1.x, q1.y, q1.z, q1.w,
                   q2.x, q2.y, q2.z, q2.w, q3.x, q3.y, q3.z, q3.w};
#pragma unroll
    for (int j = 0; j < 4; j++) {
        float a = 0.f;
#pragma unroll
        for (int k = 0; k < 11; k++) a = fmaf(gw(k), v[j + k], a);
        out[j] = a;
    }
}

__global__ __launch_bounds__(NT, 3)
void ssim_main(const float* __restrict__ pred, const float* __restrict__ targ,
               float* __restrict__ out, double inv_n) {
    extern __shared__ ull smu[];
    ull*   hp    = smu;                          // {p,t} halo pairs
    ull*   mid01 = smu + HALO_PAIRS;             // {sum_p, sum_t} pairs
    ull*   mid23 = mid01 + MID_ELEMS;            // {sum_p2, sum_t2} pairs
    float* mid4  = reinterpret_cast<float*>(mid23 + MID_ELEMS);  // sum_pt

    const int tid = threadIdx.x;
    const int tx0 = blockIdx.x * TW;
    const int ty0 = blockIdx.y * TH;
    const float* __restrict__ P = pred + (size_t)blockIdx.z * (IMG * IMG);
    const float* __restrict__ T = targ + (size_t)blockIdx.z * (IMG * IMG);

    // Packed weights {w,w} (reused by stages B and C).
    ull W2[11];
#pragma unroll
    for (int k = 0; k < 11; k++) W2[k] = pack2(gw(k), gw(k));

    // ---- Stage A: global -> SMEM halo pairs (zero pad) -------------------
#pragma unroll 4
    for (int i = tid; i < HALO_PAIRS; i += NT) {
        int sy = i / SWH;
        int sx = i - sy * SWH;
        int gy = ty0 + sy - 5;
        int gx = tx0 + sx - 5;
        float p = 0.f, t = 0.f;
        if ((unsigned)gy < (unsigned)IMG && (unsigned)gx < (unsigned)IMG) {
            p = __ldg(P + gy * IMG + gx);
            t = __ldg(T + gy * IMG + gx);
        }
        hp[i] = pack2(p, t);
    }
    __syncthreads();

    // ---- Stage B: vertical conv, pair-packed ------------------------------
    constexpr int NSTRIPS = (TH / VY) * SWH;  // 296
    for (int s = tid; s < NSTRIPS; s += NT) {
        int rg  = s / SWH;
        int x   = s - rg * SWH;
        int ry0 = rg * VY;
        ull a01[VY], a23[VY];
        float a4[VY];
#pragma unroll
        for (int j = 0; j < VY; j++) { a01[j] = 0ull; a23[j] = 0ull; a4[j] = 0.f; }
#pragma unroll
        for (int r = 0; r < VY + 10; r++) {
            ull pt01 = hp[(ry0 + r) * SWH + x];      // {p, t}
            ull pt23 = mul2(pt01, pt01);             // {p^2, t^2}
            float p, t;
            unpack2(p, t, pt01);
            float pt = p * t;
#pragma unroll
            for (int j = 0; j < VY; j++) {
                int k = r - j;
                if (k >= 0 && k < 11) {
                    a01[j] = fma2(pt01, W2[k], a01[j]);
                    a23[j] = fma2(pt23, W2[k], a23[j]);
                    a4[j]  = fmaf(gw(k), pt, a4[j]);
                }
            }
        }
#pragma unroll
        for (int j = 0; j < VY; j++) {
            int o = (ry0 + j) * SWM + x;
            mid01[o] = a01[j];
            mid23[o] = a23[j];
            mid4[o]  = a4[j];
        }
    }
    __syncthreads();

    // ---- Stage C: horizontal conv (pairs) + SSIM map + accumulate --------
    // Exactly one pass: TH*16 = 256 groups == NT. No y-tail (512 % 16 == 0).
    float local = 0.f;
    {
        int oy = tid >> 4;        // 0..15
        int x4 = tid & 15;        // output group: x0 = 4*x4

        ull m01[4], e23[4];
        float e4[4];
        hconv4_pair(mid01 + oy * SWM, x4, W2, m01);
        hconv4_pair(mid23 + oy * SWM, x4, W2, e23);
        hconv4_scalar(mid4 + oy * SWM, x4, e4);

#pragma unroll
        for (int j = 0; j < 4; j++) {
            float mu1, mu2, epp, ett;
            unpack2(mu1, mu2, m01[j]);
            unpack2(epp, ett, e23[j]);
            float mu1s = mu1 * mu1;
            float mu2s = mu2 * mu2;
            float m12  = mu1 * mu2;
            float s1   = epp - mu1s;
            float s2   = ett - mu2s;
            float s12  = e4[j] - m12;
            float num  = (2.f * m12 + SSIM_C1) * (2.f * s12 + SSIM_C2);
            float den  = (mu1s + mu2s + SSIM_C1) * (s1 + s2 + SSIM_C2);
            local += __fdividef(num, den);
        }
    }

    // ---- Block reduction -> per-block partial ----------------------------
#pragma unroll
    for (int o = 16; o > 0; o >>= 1)
        local += __shfl_xor_sync(0xffffffffu, local, o);
    __syncthreads();  // done reading mids; safe to reuse smem
    float* sf = reinterpret_cast<float*>(smu);
    if ((tid & 31) == 0) sf[tid >> 5] = local;
    __syncthreads();

    const unsigned nblocks = gridDim.x * gridDim.y * gridDim.z;
    const unsigned bid =
        blockIdx.x + gridDim.x * (blockIdx.y + gridDim.y * blockIdx.z);

    if (tid == 0) {
        float bs = 0.f;
#pragma unroll
        for (int w = 0; w < NT / 32; w++) bs += sf[w];
        g_partials[bid] = bs;
        __threadfence();
        // atomicInc wraps to 0 when reaching nblocks-1 -> self-resetting.
        unsigned ticket = atomicInc(&g_ticket, nblocks - 1u);
        sf[0] = (ticket == nblocks - 1u) ? 1.f : 0.f;
    }
    __syncthreads();

    // ---- Last block: reduce partials, write scalar ------------------------
    if (sf[0] != 0.f) {
        double acc = 0.0;
        for (unsigned i = tid; i < nblocks; i += NT)
            acc += (double)g_partials[i];
#pragma unroll
        for (int o = 16; o > 0; o >>= 1)
            acc += __shfl_xor_sync(0xffffffffu, acc, o);
        __syncthreads();
        double* dsm = reinterpret_cast<double*>(smu);
        if ((tid & 31) == 0) dsm[tid >> 5] = acc;
        __syncthreads();
        if (tid == 0) {
            double s = 0.0;
#pragma unroll
            for (int w = 0; w < NT / 32; w++) s += dsm[w];
            out[0] = (float)(1.0 - s * inv_n);
        }
    }
}

extern "C" void kernel_launch(void* const* d_in, const int* in_sizes, int n_in,
                              void* d_out, int out_size) {
    const float* pred = (const float*)d_in[0];
    const float* targ = (const float*)d_in[1];
    float* out = (float*)d_out;

    const int total  = in_sizes[0];             // 32*3*512*512
    const int planes = total / (IMG * IMG);     // 96
    const double inv_n = 1.0 / (double)total;

    static bool attr_done = false;
    if (!attr_done) {
        cudaFuncSetAttribute(ssim_main,
                             cudaFuncAttributeMaxDynamicSharedMemorySize,
                             SMEM_BYTES);
        attr_done = true;
    }

    dim3 grid(IMG / TW, IMG / TH, planes);      // 8 x 32 x 96 = 24576 blocks
    ssim_main<<<grid, NT, SMEM_BYTES>>>(pred, targ, out, inv_n);
}